// round 13
// baseline (speedup 1.0000x reference)
#include <cuda_runtime.h>
#include <cuda_bf16.h>
#include <cstdint>

// z1, z2: (4096, 256) fp32. Interleaved normalized Z: (8192, 256), quantized e4m3
// with exp scale folded in: q = sqrt(2/ln2) * z_hat, so dot_q = (2/ln2) * dot.
// loss = mean_i [ log(sum_j exp(2 z_i.z_j) - e^2 + 1e-8) - 2 z_i.z_{i^1} ]
// Symmetric: tile (IB, jb) computed iff jb >= 4*IB (A block = 256 rows,
// B block = 64 cols). Transpose term via column sums, per 128-row half,
// iff 4*IB + 2*half < (jb & ~3) -> every ordered 64-block pair counted once.
#define D        256
#define NROWS    8192
#define RB       256              // row bytes (e4m3)
#define TM       256              // CTA tile rows (i)
#define TN       64               // CTA tile cols (j)
#define NJB      (NROWS / TN)     // 128
#define NTASK    2112             // sum_{IB=0}^{31} (128 - 4*IB)
#define GRID     148
#define ABYTES   (TM * RB)        // 65536
#define BBYTES   (TN * RB)        // 16384
#define SMEM_DYN (1024 + ABYTES + 2 * BBYTES)   // 99328

#define QSCALE   1.6986436f       // sqrt(2 / ln 2)

__device__ __align__(16) uint8_t g_Zq[NROWS * RB];   // e4m3 scaled normalized rows
__device__ float g_pos[NROWS];
__device__ float g_rowsum[NROWS];

// ---------------------------------------------------------------------------
__device__ __forceinline__ uint32_t smem_u32(const void* p) {
    uint32_t a;
    asm("{ .reg .u64 t; cvta.to.shared.u64 t, %1; cvt.u32.u64 %0, t; }" : "=r"(a) : "l"(p));
    return a;
}
__device__ __forceinline__ float ex2(float x) {
    float y; asm("ex2.approx.f32 %0, %1;" : "=f"(y) : "f"(x)); return y;
}
__device__ __forceinline__ void cpa16(uint32_t dst, const void* src) {
    asm volatile("cp.async.cg.shared.global [%0], [%1], 16;" :: "r"(dst), "l"(src) : "memory");
}
#define CP_COMMIT() asm volatile("cp.async.commit_group;" ::: "memory")
#define CP_WAIT0()  asm volatile("cp.async.wait_group 0;" ::: "memory")

#define LDSM_X4(R, ADDR)                                                         \
    asm volatile("ldmatrix.sync.aligned.m8n8.x4.shared.b16 {%0,%1,%2,%3}, [%4];" \
                 : "=r"((R)[0]), "=r"((R)[1]), "=r"((R)[2]), "=r"((R)[3])        \
                 : "r"(ADDR))

__device__ __forceinline__ void mma_e4m3(float* c, const uint32_t* a, uint32_t b0, uint32_t b1) {
    asm volatile(
        "mma.sync.aligned.m16n8k32.row.col.f32.e4m3.e4m3.f32 "
        "{%0,%1,%2,%3}, {%4,%5,%6,%7}, {%8,%9}, {%0,%1,%2,%3};"
        : "+f"(c[0]), "+f"(c[1]), "+f"(c[2]), "+f"(c[3])
        : "r"(a[0]), "r"(a[1]), "r"(a[2]), "r"(a[3]), "r"(b0), "r"(b1));
}

// SW128-style swizzled tile addressing. Atom = 8 rows x 128B.
// A tile: 256 rows (32 atom-rows); B tile: 64 rows (8 atom-rows).
__device__ __forceinline__ uint32_t taddrA(int r, int b) {
    uint32_t off = ((uint32_t)(r >> 3) + ((uint32_t)(b >> 7) << 5)) * 1024u
                 + (uint32_t)(r & 7) * 128u + (uint32_t)(b & 127);
    return off ^ ((off >> 3) & 0x70);
}
__device__ __forceinline__ uint32_t taddrB(int r, int b) {
    uint32_t off = ((uint32_t)(r >> 3) + ((uint32_t)(b >> 7) << 3)) * 1024u
                 + (uint32_t)(r & 7) * 128u + (uint32_t)(b & 127);
    return off ^ ((off >> 3) & 0x70);
}

// B tile: 64 rows x 256B = 1024 x 16B chunks; 512 threads -> 2 each.
__device__ __forceinline__ void loadB(uint32_t sdst, int row0, int tid) {
    #pragma unroll
    for (int it = 0; it < 2; ++it) {
        int idx = tid + it * 512;
        int r = idx >> 4, g = idx & 15;
        cpa16(sdst + taddrB(r, g * 16), g_Zq + (size_t)(row0 + r) * RB + g * 16);
    }
}
// A tile: 256 rows -> 4096 chunks; 8 per thread.
__device__ __forceinline__ void loadA(uint32_t sdst, int row0, int tid) {
    #pragma unroll
    for (int it = 0; it < 8; ++it) {
        int idx = tid + it * 512;
        int r = idx >> 4, g = idx & 15;
        cpa16(sdst + taddrA(r, g * 16), g_Zq + (size_t)(row0 + r) * RB + g * 16);
    }
}

// ---------------------------------------------------------------------------
// prep: one warp per pair, 128-thread blocks (R9 proven). Also zeroes out[0].
// ---------------------------------------------------------------------------
__device__ __forceinline__ uint32_t pack4_e4m3(float f0, float f1, float f2, float f3) {
    uint16_t lo, hi;
    asm("cvt.rn.satfinite.e4m3x2.f32 %0, %1, %2;" : "=h"(lo) : "f"(f1), "f"(f0));
    asm("cvt.rn.satfinite.e4m3x2.f32 %0, %1, %2;" : "=h"(hi) : "f"(f3), "f"(f2));
    return (uint32_t)lo | ((uint32_t)hi << 16);
}

__global__ void __launch_bounds__(128) prep_kernel(const float* __restrict__ z1,
                                                   const float* __restrict__ z2,
                                                   float* __restrict__ out) {
    if (blockIdx.x == 0 && threadIdx.x == 0) out[0] = 0.0f;
    const int p    = blockIdx.x * 4 + (threadIdx.x >> 5);   // pair 0..4095
    const int lane = threadIdx.x & 31;
    const float4* __restrict__ p1 = reinterpret_cast<const float4*>(z1 + (size_t)p * D) + lane * 2;
    const float4* __restrict__ p2 = reinterpret_cast<const float4*>(z2 + (size_t)p * D) + lane * 2;
    const float4 a0 = p1[0];
    const float4 a1 = p1[1];
    const float4 b0 = p2[0];
    const float4 b1 = p2[1];
    float s1 = a0.x*a0.x + a0.y*a0.y + a0.z*a0.z + a0.w*a0.w
             + a1.x*a1.x + a1.y*a1.y + a1.z*a1.z + a1.w*a1.w;
    float s2 = b0.x*b0.x + b0.y*b0.y + b0.z*b0.z + b0.w*b0.w
             + b1.x*b1.x + b1.y*b1.y + b1.z*b1.z + b1.w*b1.w;
    float s3 = a0.x*b0.x + a0.y*b0.y + a0.z*b0.z + a0.w*b0.w
             + a1.x*b1.x + a1.y*b1.y + a1.z*b1.z + a1.w*b1.w;
    #pragma unroll
    for (int off = 16; off; off >>= 1) {
        s1 += __shfl_xor_sync(0xffffffffu, s1, off);
        s2 += __shfl_xor_sync(0xffffffffu, s2, off);
        s3 += __shfl_xor_sync(0xffffffffu, s3, off);
    }
    float inv1 = 1.0f / fmaxf(sqrtf(s1), 1e-12f);
    float inv2 = 1.0f / fmaxf(sqrtf(s2), 1e-12f);
    if (lane == 0) {
        float lp = 2.0f * (s3 * inv1 * inv2);
        g_pos[2*p] = lp; g_pos[2*p+1] = lp;
        g_rowsum[2*p] = 0.0f; g_rowsum[2*p+1] = 0.0f;
    }
    const float q1 = inv1 * QSCALE, q2 = inv2 * QSCALE;
    uint2 qa, qb;
    qa.x = pack4_e4m3(a0.x*q1, a0.y*q1, a0.z*q1, a0.w*q1);
    qa.y = pack4_e4m3(a1.x*q1, a1.y*q1, a1.z*q1, a1.w*q1);
    qb.x = pack4_e4m3(b0.x*q2, b0.y*q2, b0.z*q2, b0.w*q2);
    qb.y = pack4_e4m3(b1.x*q2, b1.y*q2, b1.z*q2, b1.w*q2);
    *reinterpret_cast<uint2*>(g_Zq + (size_t)(2*p)   * RB + lane * 8) = qa;
    *reinterpret_cast<uint2*>(g_Zq + (size_t)(2*p+1) * RB + lane * 8) = qb;
}

// ---------------------------------------------------------------------------
// Persistent symmetric fp8 GEMM + exp + row/col reduce (identical to R9).
// CTA: 256(i) x 64(j) tiles, K=256. 16 warps, warp tile 64x16 (grid 4m x 4n).
// ---------------------------------------------------------------------------
extern __shared__ char smem_raw[];

__device__ __forceinline__ void flush_acc(float* acc, int rowbase, int lane) {
    #pragma unroll
    for (int m = 0; m < 8; ++m) {
        float v = acc[m];
        v += __shfl_xor_sync(0xffffffffu, v, 1);
        v += __shfl_xor_sync(0xffffffffu, v, 2);
        if ((lane & 3) == 0)
            atomicAdd(&g_rowsum[rowbase + (m >> 1) * 16 + (m & 1) * 8 + (lane >> 2)], v);
        acc[m] = 0.0f;
    }
}

__global__ void __launch_bounds__(512, 1) gemm_kernel() {
    const uint32_t base = smem_u32(smem_raw);
    const uint32_t sb   = (base + 1023u) & ~1023u;
    const uint32_t sA   = sb;
    const uint32_t sB0  = sA + ABYTES;
    const uint32_t sB1  = sB0 + BBYTES;

    const int tid   = threadIdx.x;
    const int lane  = tid & 31;
    const int wid   = tid >> 5;
    const int warpM = wid & 3;        // 0..3 -> 64-row stripe
    const int warpN = wid >> 2;       // 0..3 -> 16-col stripe
    const int half  = warpM >> 1;     // 0: rows in 128-block 2*IB, 1: 2*IB+1

    uint32_t aAddr[4];
    {
        int rr  = warpM * 64 + (lane & 15);
        int sub = (lane >> 4) * 16;
        #pragma unroll
        for (int ma = 0; ma < 4; ++ma) aAddr[ma] = sA + taddrA(rr + ma * 16, sub);
    }
    uint32_t bOff;
    {
        int jo  = (lane & 7) + ((lane >> 4) << 3);
        int sub = ((lane >> 3) & 1) * 16;
        bOff = taddrB(warpN * 16 + jo, sub);
    }

    const int beg = (blockIdx.x * NTASK) / GRID;
    const int end = ((blockIdx.x + 1) * NTASK) / GRID;

    int IB = 0, rem = beg;
    while (rem >= NJB - 4 * IB) { rem -= NJB - 4 * IB; ++IB; }
    int jb = 4 * IB + rem;

    loadA(sA, IB * TM, tid);  CP_COMMIT();
    loadB(sB0, jb * TN, tid); CP_COMMIT();
    CP_WAIT0();
    __syncthreads();

    float acc[8] = {0.f, 0.f, 0.f, 0.f, 0.f, 0.f, 0.f, 0.f};

    for (int t = beg; t < end; ++t) {
        const int buf = (t - beg) & 1;
        int IBn = IB, jbn = jb + 1;
        if (jbn == NJB) { IBn = IB + 1; jbn = 4 * IBn; }
        const bool more = (t + 1 < end);
        if (more) { loadB(buf ? sB0 : sB1, jbn * TN, tid); CP_COMMIT(); }

        const uint32_t bb = buf ? sB1 : sB0;
        float c[4][2][4];
        #pragma unroll
        for (int ma = 0; ma < 4; ++ma)
            #pragma unroll
            for (int na = 0; na < 2; ++na)
                #pragma unroll
                for (int q = 0; q < 4; ++q) c[ma][na][q] = 0.0f;

        #pragma unroll
        for (int ks = 0; ks < 8; ++ks) {
            const uint32_t koA = (uint32_t)((ks & 3) * 32 + (ks >> 2) * 32768);
            const uint32_t koB = (uint32_t)((ks & 3) * 32 + (ks >> 2) * 8192);
            uint32_t a[4][4];
            #pragma unroll
            for (int ma = 0; ma < 4; ++ma) LDSM_X4(a[ma], aAddr[ma] + koA);
            uint32_t b[4];
            LDSM_X4(b, bb + bOff + koB);
            #pragma unroll
            for (int ma = 0; ma < 4; ++ma) {
                mma_e4m3(c[ma][0], a[ma], b[0], b[1]);
                mma_e4m3(c[ma][1], a[ma], b[2], b[3]);
            }
        }

        const bool doCols = (4 * IB + 2 * half) < (jb & ~3);
        float cs[2][2] = {{0.f, 0.f}, {0.f, 0.f}};
        #pragma unroll
        for (int ma = 0; ma < 4; ++ma) {
            #pragma unroll
            for (int na = 0; na < 2; ++na) {
                float e0 = ex2(c[ma][na][0]);
                float e1 = ex2(c[ma][na][1]);
                float e2 = ex2(c[ma][na][2]);
                float e3 = ex2(c[ma][na][3]);
                acc[ma * 2 + 0] += e0 + e1;      // row g
                acc[ma * 2 + 1] += e2 + e3;      // row g+8
                if (doCols) {
                    cs[na][0] += e0 + e2;        // col 2t
                    cs[na][1] += e1 + e3;        // col 2t+1
                }
            }
        }
        if (doCols) {
            #pragma unroll
            for (int na = 0; na < 2; ++na) {
                float v0 = cs[na][0], v1 = cs[na][1];
                #pragma unroll
                for (int off = 4; off < 32; off <<= 1) {
                    v0 += __shfl_xor_sync(0xffffffffu, v0, off);
                    v1 += __shfl_xor_sync(0xffffffffu, v1, off);
                }
                if (lane < 4) {
                    int j = jb * TN + warpN * 16 + na * 8 + 2 * lane;
                    atomicAdd(&g_rowsum[j],     v0);
                    atomicAdd(&g_rowsum[j + 1], v1);
                }
            }
        }

        if (more && IBn != IB) {
            flush_acc(acc, IB * TM + warpM * 64, lane);
            __syncthreads();
            loadA(sA, IBn * TM, tid);
            CP_COMMIT();
        }
        if (more) { IB = IBn; jb = jbn; }
        CP_WAIT0();
        __syncthreads();
    }

    flush_acc(acc, IB * TM + warpM * 64, lane);
}

// ---------------------------------------------------------------------------
// loss: 64 blocks x 128 threads, one row per thread; MUFU work spread over
// 64 SMs. Warp-reduce then one atomicAdd per warp into out[0] (pre-zeroed
// by prep_kernel).
// ---------------------------------------------------------------------------
__global__ void __launch_bounds__(128) loss_kernel(float* __restrict__ out) {
    const float E2 = 7.3890560989306495f;
    const int i = blockIdx.x * 128 + threadIdx.x;   // 0..8191
    float v = __logf(g_rowsum[i] - E2 + 1e-8f) - g_pos[i];
    #pragma unroll
    for (int off = 16; off; off >>= 1)
        v += __shfl_xor_sync(0xffffffffu, v, off);
    if ((threadIdx.x & 31) == 0)
        atomicAdd(out, v * (1.0f / (float)NROWS));
}

// ---------------------------------------------------------------------------
extern "C" void kernel_launch(void* const* d_in, const int* in_sizes, int n_in,
                              void* d_out, int out_size) {
    const float* z1 = (const float*)d_in[0];
    const float* z2 = (const float*)d_in[1];
    float* out = (float*)d_out;

    prep_kernel<<<NROWS / 2 / 4, 128>>>(z1, z2, out);

    cudaFuncSetAttribute(gemm_kernel, cudaFuncAttributeMaxDynamicSharedMemorySize, SMEM_DYN);
    gemm_kernel<<<GRID, 512, SMEM_DYN>>>();

    loss_kernel<<<NROWS / 128, 128>>>(out);
}

// round 14
// speedup vs baseline: 1.4857x; 1.4857x over previous
#include <cuda_runtime.h>
#include <cuda_bf16.h>
#include <cstdint>

// z1, z2: (4096, 256) fp32. Interleaved normalized Z: (8192, 256), quantized e4m3
// with exp scale folded in: q = sqrt(2/ln2) * z_hat, so dot_q = (2/ln2) * dot.
// loss = mean_i [ log(sum_j exp(2 z_i.z_j) - e^2 + 1e-8) - 2 z_i.z_{i^1} ]
// Symmetric: tile (IB, jb) computed iff jb >= 4*IB (A block = 256 rows,
// B block = 64 cols). Transpose term via column sums, per 128-row half,
// iff 4*IB + 2*half < (jb & ~3) -> every ordered 64-block pair counted once.
#define D        256
#define NROWS    8192
#define RB       256              // row bytes (e4m3)
#define TM       256              // CTA tile rows (i)
#define TN       64               // CTA tile cols (j)
#define NJB      (NROWS / TN)     // 128
#define NTASK    2112             // sum_{IB=0}^{31} (128 - 4*IB)
#define GRID     148
#define ABYTES   (TM * RB)        // 65536
#define BBYTES   (TN * RB)        // 16384
#define SMEM_DYN (1024 + ABYTES + 2 * BBYTES)   // 99328

#define QSCALE   1.6986436f       // sqrt(2 / ln 2)
#define LBLK     64               // loss stage-1 blocks

__device__ __align__(16) uint8_t g_Zq[NROWS * RB];   // e4m3 scaled normalized rows
__device__ float g_pos[NROWS];
__device__ float g_rowsum[NROWS];
__device__ float g_part[LBLK];

// ---------------------------------------------------------------------------
__device__ __forceinline__ uint32_t smem_u32(const void* p) {
    uint32_t a;
    asm("{ .reg .u64 t; cvta.to.shared.u64 t, %1; cvt.u32.u64 %0, t; }" : "=r"(a) : "l"(p));
    return a;
}
__device__ __forceinline__ float ex2(float x) {
    float y; asm("ex2.approx.f32 %0, %1;" : "=f"(y) : "f"(x)); return y;
}
__device__ __forceinline__ void cpa16(uint32_t dst, const void* src) {
    asm volatile("cp.async.cg.shared.global [%0], [%1], 16;" :: "r"(dst), "l"(src) : "memory");
}
#define CP_COMMIT() asm volatile("cp.async.commit_group;" ::: "memory")
#define CP_WAIT0()  asm volatile("cp.async.wait_group 0;" ::: "memory")

#define LDSM_X4(R, ADDR)                                                         \
    asm volatile("ldmatrix.sync.aligned.m8n8.x4.shared.b16 {%0,%1,%2,%3}, [%4];" \
                 : "=r"((R)[0]), "=r"((R)[1]), "=r"((R)[2]), "=r"((R)[3])        \
                 : "r"(ADDR))

__device__ __forceinline__ void mma_e4m3(float* c, const uint32_t* a, uint32_t b0, uint32_t b1) {
    asm volatile(
        "mma.sync.aligned.m16n8k32.row.col.f32.e4m3.e4m3.f32 "
        "{%0,%1,%2,%3}, {%4,%5,%6,%7}, {%8,%9}, {%0,%1,%2,%3};"
        : "+f"(c[0]), "+f"(c[1]), "+f"(c[2]), "+f"(c[3])
        : "r"(a[0]), "r"(a[1]), "r"(a[2]), "r"(a[3]), "r"(b0), "r"(b1));
}

// SW128-style swizzled tile addressing. Atom = 8 rows x 128B.
// A tile: 256 rows (32 atom-rows); B tile: 64 rows (8 atom-rows).
__device__ __forceinline__ uint32_t taddrA(int r, int b) {
    uint32_t off = ((uint32_t)(r >> 3) + ((uint32_t)(b >> 7) << 5)) * 1024u
                 + (uint32_t)(r & 7) * 128u + (uint32_t)(b & 127);
    return off ^ ((off >> 3) & 0x70);
}
__device__ __forceinline__ uint32_t taddrB(int r, int b) {
    uint32_t off = ((uint32_t)(r >> 3) + ((uint32_t)(b >> 7) << 3)) * 1024u
                 + (uint32_t)(r & 7) * 128u + (uint32_t)(b & 127);
    return off ^ ((off >> 3) & 0x70);
}

// B tile: 64 rows x 256B = 1024 x 16B chunks; 512 threads -> 2 each.
__device__ __forceinline__ void loadB(uint32_t sdst, int row0, int tid) {
    #pragma unroll
    for (int it = 0; it < 2; ++it) {
        int idx = tid + it * 512;
        int r = idx >> 4, g = idx & 15;
        cpa16(sdst + taddrB(r, g * 16), g_Zq + (size_t)(row0 + r) * RB + g * 16);
    }
}
// A tile: 256 rows -> 4096 chunks; 8 per thread.
__device__ __forceinline__ void loadA(uint32_t sdst, int row0, int tid) {
    #pragma unroll
    for (int it = 0; it < 8; ++it) {
        int idx = tid + it * 512;
        int r = idx >> 4, g = idx & 15;
        cpa16(sdst + taddrA(r, g * 16), g_Zq + (size_t)(row0 + r) * RB + g * 16);
    }
}

// ---------------------------------------------------------------------------
// prep: one warp per pair, 128-thread blocks (R9 proven, unchanged).
// ---------------------------------------------------------------------------
__device__ __forceinline__ uint32_t pack4_e4m3(float f0, float f1, float f2, float f3) {
    uint16_t lo, hi;
    asm("cvt.rn.satfinite.e4m3x2.f32 %0, %1, %2;" : "=h"(lo) : "f"(f1), "f"(f0));
    asm("cvt.rn.satfinite.e4m3x2.f32 %0, %1, %2;" : "=h"(hi) : "f"(f3), "f"(f2));
    return (uint32_t)lo | ((uint32_t)hi << 16);
}

__global__ void __launch_bounds__(128) prep_kernel(const float* __restrict__ z1,
                                                   const float* __restrict__ z2) {
    const int p    = blockIdx.x * 4 + (threadIdx.x >> 5);   // pair 0..4095
    const int lane = threadIdx.x & 31;
    const float4* __restrict__ p1 = reinterpret_cast<const float4*>(z1 + (size_t)p * D) + lane * 2;
    const float4* __restrict__ p2 = reinterpret_cast<const float4*>(z2 + (size_t)p * D) + lane * 2;
    const float4 a0 = p1[0];
    const float4 a1 = p1[1];
    const float4 b0 = p2[0];
    const float4 b1 = p2[1];
    float s1 = a0.x*a0.x + a0.y*a0.y + a0.z*a0.z + a0.w*a0.w
             + a1.x*a1.x + a1.y*a1.y + a1.z*a1.z + a1.w*a1.w;
    float s2 = b0.x*b0.x + b0.y*b0.y + b0.z*b0.z + b0.w*b0.w
             + b1.x*b1.x + b1.y*b1.y + b1.z*b1.z + b1.w*b1.w;
    float s3 = a0.x*b0.x + a0.y*b0.y + a0.z*b0.z + a0.w*b0.w
             + a1.x*b1.x + a1.y*b1.y + a1.z*b1.z + a1.w*b1.w;
    #pragma unroll
    for (int off = 16; off; off >>= 1) {
        s1 += __shfl_xor_sync(0xffffffffu, s1, off);
        s2 += __shfl_xor_sync(0xffffffffu, s2, off);
        s3 += __shfl_xor_sync(0xffffffffu, s3, off);
    }
    float inv1 = 1.0f / fmaxf(sqrtf(s1), 1e-12f);
    float inv2 = 1.0f / fmaxf(sqrtf(s2), 1e-12f);
    if (lane == 0) {
        float lp = 2.0f * (s3 * inv1 * inv2);
        g_pos[2*p] = lp; g_pos[2*p+1] = lp;
        g_rowsum[2*p] = 0.0f; g_rowsum[2*p+1] = 0.0f;
    }
    const float q1 = inv1 * QSCALE, q2 = inv2 * QSCALE;
    uint2 qa, qb;
    qa.x = pack4_e4m3(a0.x*q1, a0.y*q1, a0.z*q1, a0.w*q1);
    qa.y = pack4_e4m3(a1.x*q1, a1.y*q1, a1.z*q1, a1.w*q1);
    qb.x = pack4_e4m3(b0.x*q2, b0.y*q2, b0.z*q2, b0.w*q2);
    qb.y = pack4_e4m3(b1.x*q2, b1.y*q2, b1.z*q2, b1.w*q2);
    *reinterpret_cast<uint2*>(g_Zq + (size_t)(2*p)   * RB + lane * 8) = qa;
    *reinterpret_cast<uint2*>(g_Zq + (size_t)(2*p+1) * RB + lane * 8) = qb;
}

// ---------------------------------------------------------------------------
// Persistent symmetric fp8 GEMM + exp + row/col reduce (identical to R9).
// CTA: 256(i) x 64(j) tiles, K=256. 16 warps, warp tile 64x16 (grid 4m x 4n).
// ---------------------------------------------------------------------------
extern __shared__ char smem_raw[];

__device__ __forceinline__ void flush_acc(float* acc, int rowbase, int lane) {
    #pragma unroll
    for (int m = 0; m < 8; ++m) {
        float v = acc[m];
        v += __shfl_xor_sync(0xffffffffu, v, 1);
        v += __shfl_xor_sync(0xffffffffu, v, 2);
        if ((lane & 3) == 0)
            atomicAdd(&g_rowsum[rowbase + (m >> 1) * 16 + (m & 1) * 8 + (lane >> 2)], v);
        acc[m] = 0.0f;
    }
}

__global__ void __launch_bounds__(512, 1) gemm_kernel() {
    const uint32_t base = smem_u32(smem_raw);
    const uint32_t sb   = (base + 1023u) & ~1023u;
    const uint32_t sA   = sb;
    const uint32_t sB0  = sA + ABYTES;
    const uint32_t sB1  = sB0 + BBYTES;

    const int tid   = threadIdx.x;
    const int lane  = tid & 31;
    const int wid   = tid >> 5;
    const int warpM = wid & 3;        // 0..3 -> 64-row stripe
    const int warpN = wid >> 2;       // 0..3 -> 16-col stripe
    const int half  = warpM >> 1;     // 0: rows in 128-block 2*IB, 1: 2*IB+1

    uint32_t aAddr[4];
    {
        int rr  = warpM * 64 + (lane & 15);
        int sub = (lane >> 4) * 16;
        #pragma unroll
        for (int ma = 0; ma < 4; ++ma) aAddr[ma] = sA + taddrA(rr + ma * 16, sub);
    }
    uint32_t bOff;
    {
        int jo  = (lane & 7) + ((lane >> 4) << 3);
        int sub = ((lane >> 3) & 1) * 16;
        bOff = taddrB(warpN * 16 + jo, sub);
    }

    const int beg = (blockIdx.x * NTASK) / GRID;
    const int end = ((blockIdx.x + 1) * NTASK) / GRID;

    int IB = 0, rem = beg;
    while (rem >= NJB - 4 * IB) { rem -= NJB - 4 * IB; ++IB; }
    int jb = 4 * IB + rem;

    loadA(sA, IB * TM, tid);  CP_COMMIT();
    loadB(sB0, jb * TN, tid); CP_COMMIT();
    CP_WAIT0();
    __syncthreads();

    float acc[8] = {0.f, 0.f, 0.f, 0.f, 0.f, 0.f, 0.f, 0.f};

    for (int t = beg; t < end; ++t) {
        const int buf = (t - beg) & 1;
        int IBn = IB, jbn = jb + 1;
        if (jbn == NJB) { IBn = IB + 1; jbn = 4 * IBn; }
        const bool more = (t + 1 < end);
        if (more) { loadB(buf ? sB0 : sB1, jbn * TN, tid); CP_COMMIT(); }

        const uint32_t bb = buf ? sB1 : sB0;
        float c[4][2][4];
        #pragma unroll
        for (int ma = 0; ma < 4; ++ma)
            #pragma unroll
            for (int na = 0; na < 2; ++na)
                #pragma unroll
                for (int q = 0; q < 4; ++q) c[ma][na][q] = 0.0f;

        #pragma unroll
        for (int ks = 0; ks < 8; ++ks) {
            const uint32_t koA = (uint32_t)((ks & 3) * 32 + (ks >> 2) * 32768);
            const uint32_t koB = (uint32_t)((ks & 3) * 32 + (ks >> 2) * 8192);
            uint32_t a[4][4];
            #pragma unroll
            for (int ma = 0; ma < 4; ++ma) LDSM_X4(a[ma], aAddr[ma] + koA);
            uint32_t b[4];
            LDSM_X4(b, bb + bOff + koB);
            #pragma unroll
            for (int ma = 0; ma < 4; ++ma) {
                mma_e4m3(c[ma][0], a[ma], b[0], b[1]);
                mma_e4m3(c[ma][1], a[ma], b[2], b[3]);
            }
        }

        const bool doCols = (4 * IB + 2 * half) < (jb & ~3);
        float cs[2][2] = {{0.f, 0.f}, {0.f, 0.f}};
        #pragma unroll
        for (int ma = 0; ma < 4; ++ma) {
            #pragma unroll
            for (int na = 0; na < 2; ++na) {
                float e0 = ex2(c[ma][na][0]);
                float e1 = ex2(c[ma][na][1]);
                float e2 = ex2(c[ma][na][2]);
                float e3 = ex2(c[ma][na][3]);
                acc[ma * 2 + 0] += e0 + e1;      // row g
                acc[ma * 2 + 1] += e2 + e3;      // row g+8
                if (doCols) {
                    cs[na][0] += e0 + e2;        // col 2t
                    cs[na][1] += e1 + e3;        // col 2t+1
                }
            }
        }
        if (doCols) {
            #pragma unroll
            for (int na = 0; na < 2; ++na) {
                float v0 = cs[na][0], v1 = cs[na][1];
                #pragma unroll
                for (int off = 4; off < 32; off <<= 1) {
                    v0 += __shfl_xor_sync(0xffffffffu, v0, off);
                    v1 += __shfl_xor_sync(0xffffffffu, v1, off);
                }
                if (lane < 4) {
                    int j = jb * TN + warpN * 16 + na * 8 + 2 * lane;
                    atomicAdd(&g_rowsum[j],     v0);
                    atomicAdd(&g_rowsum[j + 1], v1);
                }
            }
        }

        if (more && IBn != IB) {
            flush_acc(acc, IB * TM + warpM * 64, lane);
            __syncthreads();
            loadA(sA, IBn * TM, tid);
            CP_COMMIT();
        }
        if (more) { IB = IBn; jb = jbn; }
        CP_WAIT0();
        __syncthreads();
    }

    flush_acc(acc, IB * TM + warpM * 64, lane);
}

// ---------------------------------------------------------------------------
// loss stage 1: 64 blocks x 128 threads, one row per thread (MUFU spread over
// 64 SMs), block-reduce into g_part[bid]. Deterministic.
// ---------------------------------------------------------------------------
__global__ void __launch_bounds__(128) loss1_kernel() {
    const float E2 = 7.3890560989306495f;
    const int i = blockIdx.x * 128 + threadIdx.x;   // 0..8191
    float v = __logf(g_rowsum[i] - E2 + 1e-8f) - g_pos[i];
    #pragma unroll
    for (int off = 16; off; off >>= 1)
        v += __shfl_xor_sync(0xffffffffu, v, off);
    __shared__ float sh[4];
    if ((threadIdx.x & 31) == 0) sh[threadIdx.x >> 5] = v;
    __syncthreads();
    if (threadIdx.x == 0)
        g_part[blockIdx.x] = sh[0] + sh[1] + sh[2] + sh[3];
}

// loss stage 2: one 64-thread block sums partials -> out.
__global__ void __launch_bounds__(64) loss2_kernel(float* __restrict__ out) {
    float v = g_part[threadIdx.x];
    #pragma unroll
    for (int off = 16; off; off >>= 1)
        v += __shfl_xor_sync(0xffffffffu, v, off);
    __shared__ float sh[2];
    if ((threadIdx.x & 31) == 0) sh[threadIdx.x >> 5] = v;
    __syncthreads();
    if (threadIdx.x == 0)
        out[0] = (sh[0] + sh[1]) * (1.0f / (float)NROWS);
}

// ---------------------------------------------------------------------------
extern "C" void kernel_launch(void* const* d_in, const int* in_sizes, int n_in,
                              void* d_out, int out_size) {
    const float* z1 = (const float*)d_in[0];
    const float* z2 = (const float*)d_in[1];
    float* out = (float*)d_out;

    prep_kernel<<<NROWS / 2 / 4, 128>>>(z1, z2);

    cudaFuncSetAttribute(gemm_kernel, cudaFuncAttributeMaxDynamicSharedMemorySize, SMEM_DYN);
    gemm_kernel<<<GRID, 512, SMEM_DYN>>>();

    loss1_kernel<<<LBLK, 128>>>();
    loss2_kernel<<<1, 64>>>(out);
}

// round 15
// speedup vs baseline: 1.4948x; 1.0061x over previous
#include <cuda_runtime.h>
#include <cuda_bf16.h>
#include <cstdint>

// z1, z2: (4096, 256) fp32. Interleaved normalized Z: (8192, 256), quantized e4m3
// with exp scale folded in: q = sqrt(2/ln2) * z_hat, so dot_q = (2/ln2) * dot.
// loss = mean_i [ log(sum_j exp(2 z_i.z_j) - e^2 + 1e-8) - 2 z_i.z_{i^1} ]
// Symmetric: tile (IB, jb) computed iff jb >= 4*IB (A block = 256 rows,
// B block = 64 cols). Transpose term via column sums, per 128-row half,
// iff 4*IB + 2*half < (jb & ~3) -> every ordered 64-block pair counted once.
// Loss fused into gemm behind a device-wide spin barrier (grid=148 @ occ 1 ->
// all CTAs co-resident -> deadlock-free; mechanism proven in R12).
#define D        256
#define NROWS    8192
#define RB       256              // row bytes (e4m3)
#define TM       256              // CTA tile rows (i)
#define TN       64               // CTA tile cols (j)
#define NJB      (NROWS / TN)     // 128
#define NTASK    2112             // sum_{IB=0}^{31} (128 - 4*IB)
#define GRID     148
#define ABYTES   (TM * RB)        // 65536
#define BBYTES   (TN * RB)        // 16384
#define SMEM_DYN (1024 + ABYTES + 2 * BBYTES)   // 99328

#define QSCALE   1.6986436f       // sqrt(2 / ln 2)

__device__ __align__(16) uint8_t g_Zq[NROWS * RB];   // e4m3 scaled normalized rows
__device__ float g_pos[NROWS];
__device__ float g_rowsum[NROWS];
__device__ int   g_ctr;           // barrier counter; reset by prep each replay

// ---------------------------------------------------------------------------
__device__ __forceinline__ uint32_t smem_u32(const void* p) {
    uint32_t a;
    asm("{ .reg .u64 t; cvta.to.shared.u64 t, %1; cvt.u32.u64 %0, t; }" : "=r"(a) : "l"(p));
    return a;
}
__device__ __forceinline__ float ex2(float x) {
    float y; asm("ex2.approx.f32 %0, %1;" : "=f"(y) : "f"(x)); return y;
}
__device__ __forceinline__ void cpa16(uint32_t dst, const void* src) {
    asm volatile("cp.async.cg.shared.global [%0], [%1], 16;" :: "r"(dst), "l"(src) : "memory");
}
#define CP_COMMIT() asm volatile("cp.async.commit_group;" ::: "memory")
#define CP_WAIT0()  asm volatile("cp.async.wait_group 0;" ::: "memory")

#define LDSM_X4(R, ADDR)                                                         \
    asm volatile("ldmatrix.sync.aligned.m8n8.x4.shared.b16 {%0,%1,%2,%3}, [%4];" \
                 : "=r"((R)[0]), "=r"((R)[1]), "=r"((R)[2]), "=r"((R)[3])        \
                 : "r"(ADDR))

__device__ __forceinline__ void mma_e4m3(float* c, const uint32_t* a, uint32_t b0, uint32_t b1) {
    asm volatile(
        "mma.sync.aligned.m16n8k32.row.col.f32.e4m3.e4m3.f32 "
        "{%0,%1,%2,%3}, {%4,%5,%6,%7}, {%8,%9}, {%0,%1,%2,%3};"
        : "+f"(c[0]), "+f"(c[1]), "+f"(c[2]), "+f"(c[3])
        : "r"(a[0]), "r"(a[1]), "r"(a[2]), "r"(a[3]), "r"(b0), "r"(b1));
}

// SW128-style swizzled tile addressing. Atom = 8 rows x 128B.
__device__ __forceinline__ uint32_t taddrA(int r, int b) {
    uint32_t off = ((uint32_t)(r >> 3) + ((uint32_t)(b >> 7) << 5)) * 1024u
                 + (uint32_t)(r & 7) * 128u + (uint32_t)(b & 127);
    return off ^ ((off >> 3) & 0x70);
}
__device__ __forceinline__ uint32_t taddrB(int r, int b) {
    uint32_t off = ((uint32_t)(r >> 3) + ((uint32_t)(b >> 7) << 3)) * 1024u
                 + (uint32_t)(r & 7) * 128u + (uint32_t)(b & 127);
    return off ^ ((off >> 3) & 0x70);
}

// B tile: 64 rows x 256B = 1024 x 16B chunks; 512 threads -> 2 each.
__device__ __forceinline__ void loadB(uint32_t sdst, int row0, int tid) {
    #pragma unroll
    for (int it = 0; it < 2; ++it) {
        int idx = tid + it * 512;
        int r = idx >> 4, g = idx & 15;
        cpa16(sdst + taddrB(r, g * 16), g_Zq + (size_t)(row0 + r) * RB + g * 16);
    }
}
// A tile: 256 rows -> 4096 chunks; 8 per thread.
__device__ __forceinline__ void loadA(uint32_t sdst, int row0, int tid) {
    #pragma unroll
    for (int it = 0; it < 8; ++it) {
        int idx = tid + it * 512;
        int r = idx >> 4, g = idx & 15;
        cpa16(sdst + taddrA(r, g * 16), g_Zq + (size_t)(row0 + r) * RB + g * 16);
    }
}

// ---------------------------------------------------------------------------
// prep: one warp per pair (R9 proven body). Thread 0 of block 0 also zeroes
// out[0] and the gemm barrier counter (runs before gemm in every replay).
// ---------------------------------------------------------------------------
__device__ __forceinline__ uint32_t pack4_e4m3(float f0, float f1, float f2, float f3) {
    uint16_t lo, hi;
    asm("cvt.rn.satfinite.e4m3x2.f32 %0, %1, %2;" : "=h"(lo) : "f"(f1), "f"(f0));
    asm("cvt.rn.satfinite.e4m3x2.f32 %0, %1, %2;" : "=h"(hi) : "f"(f3), "f"(f2));
    return (uint32_t)lo | ((uint32_t)hi << 16);
}

__global__ void __launch_bounds__(128) prep_kernel(const float* __restrict__ z1,
                                                   const float* __restrict__ z2,
                                                   float* __restrict__ out) {
    if (blockIdx.x == 0 && threadIdx.x == 0) { out[0] = 0.0f; g_ctr = 0; }
    const int p    = blockIdx.x * 4 + (threadIdx.x >> 5);   // pair 0..4095
    const int lane = threadIdx.x & 31;
    const float4* __restrict__ p1 = reinterpret_cast<const float4*>(z1 + (size_t)p * D) + lane * 2;
    const float4* __restrict__ p2 = reinterpret_cast<const float4*>(z2 + (size_t)p * D) + lane * 2;
    const float4 a0 = p1[0];
    const float4 a1 = p1[1];
    const float4 b0 = p2[0];
    const float4 b1 = p2[1];
    float s1 = a0.x*a0.x + a0.y*a0.y + a0.z*a0.z + a0.w*a0.w
             + a1.x*a1.x + a1.y*a1.y + a1.z*a1.z + a1.w*a1.w;
    float s2 = b0.x*b0.x + b0.y*b0.y + b0.z*b0.z + b0.w*b0.w
             + b1.x*b1.x + b1.y*b1.y + b1.z*b1.z + b1.w*b1.w;
    float s3 = a0.x*b0.x + a0.y*b0.y + a0.z*b0.z + a0.w*b0.w
             + a1.x*b1.x + a1.y*b1.y + a1.z*b1.z + a1.w*b1.w;
    #pragma unroll
    for (int off = 16; off; off >>= 1) {
        s1 += __shfl_xor_sync(0xffffffffu, s1, off);
        s2 += __shfl_xor_sync(0xffffffffu, s2, off);
        s3 += __shfl_xor_sync(0xffffffffu, s3, off);
    }
    float inv1 = 1.0f / fmaxf(sqrtf(s1), 1e-12f);
    float inv2 = 1.0f / fmaxf(sqrtf(s2), 1e-12f);
    if (lane == 0) {
        float lp = 2.0f * (s3 * inv1 * inv2);
        g_pos[2*p] = lp; g_pos[2*p+1] = lp;
        g_rowsum[2*p] = 0.0f; g_rowsum[2*p+1] = 0.0f;
    }
    const float q1 = inv1 * QSCALE, q2 = inv2 * QSCALE;
    uint2 qa, qb;
    qa.x = pack4_e4m3(a0.x*q1, a0.y*q1, a0.z*q1, a0.w*q1);
    qa.y = pack4_e4m3(a1.x*q1, a1.y*q1, a1.z*q1, a1.w*q1);
    qb.x = pack4_e4m3(b0.x*q2, b0.y*q2, b0.z*q2, b0.w*q2);
    qb.y = pack4_e4m3(b1.x*q2, b1.y*q2, b1.z*q2, b1.w*q2);
    *reinterpret_cast<uint2*>(g_Zq + (size_t)(2*p)   * RB + lane * 8) = qa;
    *reinterpret_cast<uint2*>(g_Zq + (size_t)(2*p+1) * RB + lane * 8) = qb;
}

// ---------------------------------------------------------------------------
// Persistent symmetric fp8 GEMM + exp + row/col reduce (R9 loop) + fused loss
// behind a device-wide barrier.
// CTA: 256(i) x 64(j) tiles, K=256. 16 warps, warp tile 64x16 (grid 4m x 4n).
// ---------------------------------------------------------------------------
extern __shared__ char smem_raw[];

__device__ __forceinline__ void flush_acc(float* acc, int rowbase, int lane) {
    #pragma unroll
    for (int m = 0; m < 8; ++m) {
        float v = acc[m];
        v += __shfl_xor_sync(0xffffffffu, v, 1);
        v += __shfl_xor_sync(0xffffffffu, v, 2);
        if ((lane & 3) == 0)
            atomicAdd(&g_rowsum[rowbase + (m >> 1) * 16 + (m & 1) * 8 + (lane >> 2)], v);
        acc[m] = 0.0f;
    }
}

__global__ void __launch_bounds__(512, 1) gemm_kernel(float* __restrict__ out) {
    const uint32_t base = smem_u32(smem_raw);
    const uint32_t sb   = (base + 1023u) & ~1023u;
    const uint32_t sA   = sb;
    const uint32_t sB0  = sA + ABYTES;
    const uint32_t sB1  = sB0 + BBYTES;

    const int tid   = threadIdx.x;
    const int lane  = tid & 31;
    const int wid   = tid >> 5;
    const int warpM = wid & 3;        // 0..3 -> 64-row stripe
    const int warpN = wid >> 2;       // 0..3 -> 16-col stripe
    const int half  = warpM >> 1;     // 0: rows in 128-block 2*IB, 1: 2*IB+1

    uint32_t aAddr[4];
    {
        int rr  = warpM * 64 + (lane & 15);
        int sub = (lane >> 4) * 16;
        #pragma unroll
        for (int ma = 0; ma < 4; ++ma) aAddr[ma] = sA + taddrA(rr + ma * 16, sub);
    }
    uint32_t bOff;
    {
        int jo  = (lane & 7) + ((lane >> 4) << 3);
        int sub = ((lane >> 3) & 1) * 16;
        bOff = taddrB(warpN * 16 + jo, sub);
    }

    const int beg = (blockIdx.x * NTASK) / GRID;
    const int end = ((blockIdx.x + 1) * NTASK) / GRID;

    int IB = 0, rem = beg;
    while (rem >= NJB - 4 * IB) { rem -= NJB - 4 * IB; ++IB; }
    int jb = 4 * IB + rem;

    loadA(sA, IB * TM, tid);  CP_COMMIT();
    loadB(sB0, jb * TN, tid); CP_COMMIT();
    CP_WAIT0();
    __syncthreads();

    float acc[8] = {0.f, 0.f, 0.f, 0.f, 0.f, 0.f, 0.f, 0.f};

    for (int t = beg; t < end; ++t) {
        const int buf = (t - beg) & 1;
        int IBn = IB, jbn = jb + 1;
        if (jbn == NJB) { IBn = IB + 1; jbn = 4 * IBn; }
        const bool more = (t + 1 < end);
        if (more) { loadB(buf ? sB0 : sB1, jbn * TN, tid); CP_COMMIT(); }

        const uint32_t bb = buf ? sB1 : sB0;
        float c[4][2][4];
        #pragma unroll
        for (int ma = 0; ma < 4; ++ma)
            #pragma unroll
            for (int na = 0; na < 2; ++na)
                #pragma unroll
                for (int q = 0; q < 4; ++q) c[ma][na][q] = 0.0f;

        #pragma unroll
        for (int ks = 0; ks < 8; ++ks) {
            const uint32_t koA = (uint32_t)((ks & 3) * 32 + (ks >> 2) * 32768);
            const uint32_t koB = (uint32_t)((ks & 3) * 32 + (ks >> 2) * 8192);
            uint32_t a[4][4];
            #pragma unroll
            for (int ma = 0; ma < 4; ++ma) LDSM_X4(a[ma], aAddr[ma] + koA);
            uint32_t b[4];
            LDSM_X4(b, bb + bOff + koB);
            #pragma unroll
            for (int ma = 0; ma < 4; ++ma) {
                mma_e4m3(c[ma][0], a[ma], b[0], b[1]);
                mma_e4m3(c[ma][1], a[ma], b[2], b[3]);
            }
        }

        const bool doCols = (4 * IB + 2 * half) < (jb & ~3);
        float cs[2][2] = {{0.f, 0.f}, {0.f, 0.f}};
        #pragma unroll
        for (int ma = 0; ma < 4; ++ma) {
            #pragma unroll
            for (int na = 0; na < 2; ++na) {
                float e0 = ex2(c[ma][na][0]);
                float e1 = ex2(c[ma][na][1]);
                float e2 = ex2(c[ma][na][2]);
                float e3 = ex2(c[ma][na][3]);
                acc[ma * 2 + 0] += e0 + e1;      // row g
                acc[ma * 2 + 1] += e2 + e3;      // row g+8
                if (doCols) {
                    cs[na][0] += e0 + e2;        // col 2t
                    cs[na][1] += e1 + e3;        // col 2t+1
                }
            }
        }
        if (doCols) {
            #pragma unroll
            for (int na = 0; na < 2; ++na) {
                float v0 = cs[na][0], v1 = cs[na][1];
                #pragma unroll
                for (int off = 4; off < 32; off <<= 1) {
                    v0 += __shfl_xor_sync(0xffffffffu, v0, off);
                    v1 += __shfl_xor_sync(0xffffffffu, v1, off);
                }
                if (lane < 4) {
                    int j = jb * TN + warpN * 16 + na * 8 + 2 * lane;
                    atomicAdd(&g_rowsum[j],     v0);
                    atomicAdd(&g_rowsum[j + 1], v1);
                }
            }
        }

        if (more && IBn != IB) {
            flush_acc(acc, IB * TM + warpM * 64, lane);
            __syncthreads();
            loadA(sA, IBn * TM, tid);
            CP_COMMIT();
        }
        if (more) { IB = IBn; jb = jbn; }
        CP_WAIT0();
        __syncthreads();
    }

    flush_acc(acc, IB * TM + warpM * 64, lane);

    // ---- device-wide barrier: all rowsum atomics complete ----
    __threadfence();
    __syncthreads();
    if (tid == 0) {
        atomicAdd(&g_ctr, 1);
        while (*(volatile int*)&g_ctr < GRID) { }
    }
    __syncthreads();

    // ---- fused loss: CTAs 0..15 cover all 8192 rows (one per thread) ----
    if (blockIdx.x < 16) {
        const float E2 = 7.3890560989306495f;
        const int i = blockIdx.x * 512 + tid;
        float v = __logf(__ldcg(&g_rowsum[i]) - E2 + 1e-8f) - g_pos[i];
        #pragma unroll
        for (int off = 16; off; off >>= 1)
            v += __shfl_xor_sync(0xffffffffu, v, off);
        __shared__ float sh[16];
        if (lane == 0) sh[wid] = v;
        __syncthreads();
        if (tid == 0) {
            float s = 0.f;
            #pragma unroll
            for (int w = 0; w < 16; ++w) s += sh[w];
            atomicAdd(out, s * (1.0f / (float)NROWS));
        }
    }
}

// ---------------------------------------------------------------------------
extern "C" void kernel_launch(void* const* d_in, const int* in_sizes, int n_in,
                              void* d_out, int out_size) {
    const float* z1 = (const float*)d_in[0];
    const float* z2 = (const float*)d_in[1];
    float* out = (float*)d_out;

    prep_kernel<<<NROWS / 2 / 4, 128>>>(z1, z2, out);

    cudaFuncSetAttribute(gemm_kernel, cudaFuncAttributeMaxDynamicSharedMemorySize, SMEM_DYN);
    gemm_kernel<<<GRID, 512, SMEM_DYN>>>(out);
}